// round 5
// baseline (speedup 1.0000x reference)
#include <cuda_runtime.h>
#include <cstdint>
#include <cstddef>

#define S_LEN 4096
#define BATCH 8
#define DH    512
#define DIN   2048
#define M_TOT (S_LEN * BATCH)
#define CLUSTER 16
#define RPC   32          // rows per CTA = DH/CLUSTER

__device__ float g_seq[(size_t)M_TOT * DH];
__device__ float g_G[(size_t)M_TOT * 3 * DH];

// ---------------- GEMM1: seq = x @ Wlm^T  (M=32768,N=512,K=2048) ----------------
__global__ __launch_bounds__(256) void gemm1_kernel(const float* __restrict__ x,
                                                    const float* __restrict__ Wlm) {
    __shared__ float As[128][17], Bs[64][17];
    const int m0 = blockIdx.y * 128, n0 = blockIdx.x * 64, tid = threadIdx.x;
    const int ty = tid >> 4, tx = tid & 15;
    float acc[8][4] = {};
    for (int k0 = 0; k0 < DIN; k0 += 16) {
#pragma unroll
        for (int i = 0; i < 2; i++) {
            int ld = tid + i * 256, r = ld >> 2, q = ld & 3;
            int m = m0 + r, b = m & 7, t = m >> 3;
            float4 v = *reinterpret_cast<const float4*>(x + ((size_t)b * S_LEN + t) * DIN + k0 + q * 4);
            As[r][q*4] = v.x; As[r][q*4+1] = v.y; As[r][q*4+2] = v.z; As[r][q*4+3] = v.w;
        }
        { int r = tid >> 2, q = tid & 3;
          float4 v = *reinterpret_cast<const float4*>(Wlm + (size_t)(n0 + r) * DIN + k0 + q * 4);
          Bs[r][q*4] = v.x; Bs[r][q*4+1] = v.y; Bs[r][q*4+2] = v.z; Bs[r][q*4+3] = v.w; }
        __syncthreads();
#pragma unroll
        for (int kk = 0; kk < 16; kk++) {
            float a[8], bb[4];
#pragma unroll
            for (int i = 0; i < 8; i++) a[i] = As[ty*8+i][kk];
#pragma unroll
            for (int j = 0; j < 4; j++) bb[j] = Bs[tx*4+j][kk];
#pragma unroll
            for (int i = 0; i < 8; i++)
#pragma unroll
                for (int j = 0; j < 4; j++) acc[i][j] = fmaf(a[i], bb[j], acc[i][j]);
        }
        __syncthreads();
    }
#pragma unroll
    for (int i = 0; i < 8; i++)
#pragma unroll
        for (int j = 0; j < 4; j++)
            g_seq[(size_t)(m0 + ty*8+i) * DH + n0 + tx*4+j] = acc[i][j];
}

// ---------------- GEMM2: G = seq @ [Wzx|Wrx|Whx]^T  (M=32768,N=1536,K=512) ------
__global__ __launch_bounds__(256) void gemm2_kernel(const float* __restrict__ Wz,
                                                    const float* __restrict__ Wr,
                                                    const float* __restrict__ Wh) {
    __shared__ float As[128][17], Bs[64][17];
    const int m0 = blockIdx.y * 128, n0 = blockIdx.x * 64, tid = threadIdx.x;
    const int ty = tid >> 4, tx = tid & 15;
    const float* base = (n0 < 512) ? Wz : (n0 < 1024) ? Wr : Wh;
    const int br0 = n0 & 511;
    float acc[8][4] = {};
    for (int k0 = 0; k0 < DH; k0 += 16) {
#pragma unroll
        for (int i = 0; i < 2; i++) {
            int ld = tid + i * 256, r = ld >> 2, q = ld & 3;
            float4 v = *reinterpret_cast<const float4*>(g_seq + (size_t)(m0 + r) * DH + k0 + q * 4);
            As[r][q*4] = v.x; As[r][q*4+1] = v.y; As[r][q*4+2] = v.z; As[r][q*4+3] = v.w;
        }
        { int r = tid >> 2, q = tid & 3;   // x-half: cols [0,512)
          float4 v = *reinterpret_cast<const float4*>(base + (size_t)(br0 + r) * 1024 + k0 + q * 4);
          Bs[r][q*4] = v.x; Bs[r][q*4+1] = v.y; Bs[r][q*4+2] = v.z; Bs[r][q*4+3] = v.w; }
        __syncthreads();
#pragma unroll
        for (int kk = 0; kk < 16; kk++) {
            float a[8], bb[4];
#pragma unroll
            for (int i = 0; i < 8; i++) a[i] = As[ty*8+i][kk];
#pragma unroll
            for (int j = 0; j < 4; j++) bb[j] = Bs[tx*4+j][kk];
#pragma unroll
            for (int i = 0; i < 8; i++)
#pragma unroll
                for (int j = 0; j < 4; j++) acc[i][j] = fmaf(a[i], bb[j], acc[i][j]);
        }
        __syncthreads();
    }
#pragma unroll
    for (int i = 0; i < 8; i++)
#pragma unroll
        for (int j = 0; j < 4; j++)
            g_G[(size_t)(m0 + ty*8+i) * 1536 + n0 + tx*4+j] = acc[i][j];
}

// ---------------- cluster helpers ----------------
__device__ __forceinline__ uint32_t smem_u32(const void* p) {
    return (uint32_t)__cvta_generic_to_shared(p);
}
__device__ __forceinline__ uint32_t dsmem_map(uint32_t laddr, unsigned rank) {
    uint32_t ra;
    asm("mapa.shared::cluster.u32 %0, %1, %2;" : "=r"(ra) : "r"(laddr), "r"(rank));
    return ra;
}
__device__ __forceinline__ void dsmem_st(uint32_t raddr, float v) {
    asm volatile("st.shared::cluster.f32 [%0], %1;" :: "r"(raddr), "f"(v) : "memory");
}
__device__ __forceinline__ void cluster_sync() {
    asm volatile("barrier.cluster.arrive.aligned;" ::: "memory");   // release
    asm volatile("barrier.cluster.wait.aligned;"   ::: "memory");   // acquire
}

// ---------------- GRU recurrence: 8 clusters x 16 CTAs x 512 threads -----------
// CTA (cluster rank c) owns h-rows [32c, 32c+32) of its batch.
// Gate weights register-resident: stage1 (z|r) 64 f32/thread, stage2 (h') 32 f32.
__global__ void __cluster_dims__(CLUSTER, 1, 1) __launch_bounds__(512, 1)
gru_kernel(const float* __restrict__ Wz, const float* __restrict__ Wr,
           const float* __restrict__ Wh, const float* __restrict__ Wc,
           float* __restrict__ out) {
    __shared__ __align__(16) float hbuf[2][DH];
    __shared__ __align__(16) float rhbuf[DH];
    __shared__ float zbuf[RPC];

    const int tid = threadIdx.x;
    unsigned rank;
    asm("mov.u32 %0, %%cluster_ctarank;" : "=r"(rank));
    const int b  = blockIdx.x / CLUSTER;
    const int j0 = (int)rank * RPC;

    // stage1 role: rowgate rg in [0,64) (z rows then r rows), k-segment of 64
    const int rg  = tid >> 3, seg = tid & 7;
    const bool is_r = rg >= 32;
    const int s1row = j0 + (rg & 31);
    // stage2 role: row r2 in [0,32), k-segment of 32
    const int r2 = tid >> 4, s16 = tid & 15;

    // register-resident weights (h-halves: cols [512,1024))
    float w1[64];
    {
        const float* W = is_r ? Wr : Wz;
        const float4* p = reinterpret_cast<const float4*>(W + (size_t)s1row * 1024 + 512 + seg * 64);
#pragma unroll
        for (int q = 0; q < 16; q++) {
            float4 v = p[q];
            w1[q*4] = v.x; w1[q*4+1] = v.y; w1[q*4+2] = v.z; w1[q*4+3] = v.w;
        }
    }
    float w2[32];
    {
        const float4* p = reinterpret_cast<const float4*>(Wh + (size_t)(j0 + r2) * 1024 + 512 + s16 * 32);
#pragma unroll
        for (int q = 0; q < 8; q++) {
            float4 v = p[q];
            w2[q*4] = v.x; w2[q*4+1] = v.y; w2[q*4+2] = v.z; w2[q*4+3] = v.w;
        }
    }

    for (int i = tid; i < 2 * DH; i += 512) (&hbuf[0][0])[i] = 0.f;

    // precompute DSMEM remote addresses (constant across steps)
    const uint32_t rh_l   = smem_u32(&rhbuf[s1row]);
    const uint32_t rh_ra  = dsmem_map(rh_l, (unsigned)seg);
    const uint32_t rh_rb  = dsmem_map(rh_l, (unsigned)(seg + 8));
    const uint32_t h_r0   = dsmem_map(smem_u32(&hbuf[0][j0 + r2]), (unsigned)s16);
    const uint32_t h_r1   = dsmem_map(smem_u32(&hbuf[1][j0 + r2]), (unsigned)s16);

    cluster_sync();   // hbuf zeroed everywhere before first pushes/reads

    int p = 0;
    for (int t = 0; t < S_LEN; t++) {
        const size_t gbase = ((size_t)t * BATCH + b) * 1536;
        const float gx1 = __ldcs(g_G + gbase + (is_r ? 512 : 0) + s1row);
        const float gx2 = __ldcs(g_G + gbase + 1024 + j0 + r2);

        // ---- stage 1: z | r pre-activations over h ----
        float acc = 0.f;
        const float4* hp = reinterpret_cast<const float4*>(&hbuf[p][seg * 64]);
#pragma unroll
        for (int q = 0; q < 16; q++) {
            float4 h4 = hp[q];
            acc = fmaf(w1[q*4],   h4.x, acc);
            acc = fmaf(w1[q*4+1], h4.y, acc);
            acc = fmaf(w1[q*4+2], h4.z, acc);
            acc = fmaf(w1[q*4+3], h4.w, acc);
        }
        acc += __shfl_xor_sync(~0u, acc, 1);
        acc += __shfl_xor_sync(~0u, acc, 2);
        acc += __shfl_xor_sync(~0u, acc, 4);
        const float gate = 1.f / (1.f + expf(-(acc + gx1)));
        if (!is_r) {
            if (seg == 0) zbuf[rg] = gate;
        } else {
            const float rh = gate * hbuf[p][s1row];
            dsmem_st(rh_ra, rh);
            dsmem_st(rh_rb, rh);
        }
        cluster_sync();

        // ---- stage 2: h' over r*h, then h update ----
        float acc2 = 0.f;
        const float4* rp = reinterpret_cast<const float4*>(&rhbuf[s16 * 32]);
#pragma unroll
        for (int q = 0; q < 8; q++) {
            float4 v = rp[q];
            acc2 = fmaf(w2[q*4],   v.x, acc2);
            acc2 = fmaf(w2[q*4+1], v.y, acc2);
            acc2 = fmaf(w2[q*4+2], v.z, acc2);
            acc2 = fmaf(w2[q*4+3], v.w, acc2);
        }
        acc2 += __shfl_xor_sync(~0u, acc2, 1);
        acc2 += __shfl_xor_sync(~0u, acc2, 2);
        acc2 += __shfl_xor_sync(~0u, acc2, 4);
        acc2 += __shfl_xor_sync(~0u, acc2, 8);
        const float hcand = tanhf(acc2 + gx2);
        const float z     = zbuf[r2];
        const float hold  = hbuf[p][j0 + r2];
        const float hnew  = hold + z * (hcand - hold);
        dsmem_st(p ? h_r0 : h_r1, hnew);   // write into hbuf[p^1] of peer s16
        cluster_sync();
        p ^= 1;
    }

    // classifier: final h (in hbuf[0], since S_LEN is even) -> out[b][10]
    if (rank == 0) {
        const int w = tid >> 5, lane = tid & 31;
        if (w < 10) {
            float s = 0.f;
            for (int k = lane; k < DH; k += 32)
                s += hbuf[0][k] * Wc[(size_t)w * DH + k];
#pragma unroll
            for (int d = 16; d; d >>= 1) s += __shfl_xor_sync(~0u, s, d);
            if (lane == 0) out[b * 10 + w] = s;
        }
    }
}

extern "C" void kernel_launch(void* const* d_in, const int* in_sizes, int n_in,
                              void* d_out, int out_size) {
    const float* x   = (const float*)d_in[0];
    const float* Wlm = (const float*)d_in[1];
    const float* Wz  = (const float*)d_in[2];
    const float* Wr  = (const float*)d_in[3];
    const float* Wh  = (const float*)d_in[4];
    const float* Wc  = (const float*)d_in[5];
    float* out = (float*)d_out;

    cudaFuncSetAttribute(gru_kernel, cudaFuncAttributeNonPortableClusterSizeAllowed, 1);

    gemm1_kernel<<<dim3(8, 256), 256>>>(x, Wlm);
    gemm2_kernel<<<dim3(24, 256), 256>>>(Wz, Wr, Wh);
    gru_kernel<<<BATCH * CLUSTER, 512>>>(Wz, Wr, Wh, Wc, out);
}

// round 6
// speedup vs baseline: 1.9779x; 1.9779x over previous
#include <cuda_runtime.h>
#include <cstdint>
#include <cstddef>

#define S_LEN 4096
#define BATCH 8
#define DH    512
#define DIN   2048
#define M_TOT (S_LEN * BATCH)
#define CLUSTER 16
#define RPC   32                  // h-rows per CTA
#define GRU_SMEM_FLOATS (96*512 + 2*512 + 512 + 32)   // wzr+wh, hbuf[2], rhbuf, zbuf

__device__ float g_seq[(size_t)M_TOT * DH];
__device__ float g_G[(size_t)M_TOT * 3 * DH];

// ---------------- GEMM1: seq = x @ Wlm^T (M=32768,N=512,K=2048) ----------------
__global__ __launch_bounds__(256) void gemm1_kernel(const float* __restrict__ x,
                                                    const float* __restrict__ Wlm) {
    __shared__ float As[128][17], Bs[64][17];
    const int m0 = blockIdx.y * 128, n0 = blockIdx.x * 64, tid = threadIdx.x;
    const int ty = tid >> 4, tx = tid & 15;
    float acc[8][4] = {};
    for (int k0 = 0; k0 < DIN; k0 += 16) {
#pragma unroll
        for (int i = 0; i < 2; i++) {
            int ld = tid + i * 256, r = ld >> 2, q = ld & 3;
            int m = m0 + r, b = m & 7, t = m >> 3;
            float4 v = *reinterpret_cast<const float4*>(x + ((size_t)b * S_LEN + t) * DIN + k0 + q * 4);
            As[r][q*4] = v.x; As[r][q*4+1] = v.y; As[r][q*4+2] = v.z; As[r][q*4+3] = v.w;
        }
        { int r = tid >> 2, q = tid & 3;
          float4 v = *reinterpret_cast<const float4*>(Wlm + (size_t)(n0 + r) * DIN + k0 + q * 4);
          Bs[r][q*4] = v.x; Bs[r][q*4+1] = v.y; Bs[r][q*4+2] = v.z; Bs[r][q*4+3] = v.w; }
        __syncthreads();
#pragma unroll
        for (int kk = 0; kk < 16; kk++) {
            float a[8], bb[4];
#pragma unroll
            for (int i = 0; i < 8; i++) a[i] = As[ty*8+i][kk];
#pragma unroll
            for (int j = 0; j < 4; j++) bb[j] = Bs[tx*4+j][kk];
#pragma unroll
            for (int i = 0; i < 8; i++)
#pragma unroll
                for (int j = 0; j < 4; j++) acc[i][j] = fmaf(a[i], bb[j], acc[i][j]);
        }
        __syncthreads();
    }
#pragma unroll
    for (int i = 0; i < 8; i++)
#pragma unroll
        for (int j = 0; j < 4; j++)
            g_seq[(size_t)(m0 + ty*8+i) * DH + n0 + tx*4+j] = acc[i][j];
}

// ------------- GEMM2: G = seq @ [Wzx|Wrx|Whx]^T (M=32768,N=1536,K=512) ---------
__global__ __launch_bounds__(256) void gemm2_kernel(const float* __restrict__ Wz,
                                                    const float* __restrict__ Wr,
                                                    const float* __restrict__ Wh) {
    __shared__ float As[128][17], Bs[64][17];
    const int m0 = blockIdx.y * 128, n0 = blockIdx.x * 64, tid = threadIdx.x;
    const int ty = tid >> 4, tx = tid & 15;
    const float* base = (n0 < 512) ? Wz : (n0 < 1024) ? Wr : Wh;
    const int br0 = n0 & 511;
    float acc[8][4] = {};
    for (int k0 = 0; k0 < DH; k0 += 16) {
#pragma unroll
        for (int i = 0; i < 2; i++) {
            int ld = tid + i * 256, r = ld >> 2, q = ld & 3;
            float4 v = *reinterpret_cast<const float4*>(g_seq + (size_t)(m0 + r) * DH + k0 + q * 4);
            As[r][q*4] = v.x; As[r][q*4+1] = v.y; As[r][q*4+2] = v.z; As[r][q*4+3] = v.w;
        }
        { int r = tid >> 2, q = tid & 3;
          float4 v = *reinterpret_cast<const float4*>(base + (size_t)(br0 + r) * 1024 + k0 + q * 4);
          Bs[r][q*4] = v.x; Bs[r][q*4+1] = v.y; Bs[r][q*4+2] = v.z; Bs[r][q*4+3] = v.w; }
        __syncthreads();
#pragma unroll
        for (int kk = 0; kk < 16; kk++) {
            float a[8], bb[4];
#pragma unroll
            for (int i = 0; i < 8; i++) a[i] = As[ty*8+i][kk];
#pragma unroll
            for (int j = 0; j < 4; j++) bb[j] = Bs[tx*4+j][kk];
#pragma unroll
            for (int i = 0; i < 8; i++)
#pragma unroll
                for (int j = 0; j < 4; j++) acc[i][j] = fmaf(a[i], bb[j], acc[i][j]);
        }
        __syncthreads();
    }
#pragma unroll
    for (int i = 0; i < 8; i++)
#pragma unroll
        for (int j = 0; j < 4; j++)
            g_G[(size_t)(m0 + ty*8+i) * 1536 + n0 + tx*4+j] = acc[i][j];
}

// ---------------- cluster helpers ----------------
__device__ __forceinline__ uint32_t smem_u32(const void* p) {
    return (uint32_t)__cvta_generic_to_shared(p);
}
__device__ __forceinline__ uint32_t dsmem_map(uint32_t laddr, unsigned rank) {
    uint32_t ra;
    asm("mapa.shared::cluster.u32 %0, %1, %2;" : "=r"(ra) : "r"(laddr), "r"(rank));
    return ra;
}
__device__ __forceinline__ void dsmem_st(uint32_t raddr, float v) {
    asm volatile("st.shared::cluster.f32 [%0], %1;" :: "r"(raddr), "f"(v) : "memory");
}
__device__ __forceinline__ void cluster_sync() {
    asm volatile("barrier.cluster.arrive.aligned;" ::: "memory");
    asm volatile("barrier.cluster.wait.aligned;"   ::: "memory");
}

// ------- GRU: 8 clusters x 16 CTAs x 512 thr; weights smem-stationary ----------
__global__ void __cluster_dims__(CLUSTER, 1, 1) __launch_bounds__(512, 1)
gru_kernel(const float* __restrict__ Wz, const float* __restrict__ Wr,
           const float* __restrict__ Wh, const float* __restrict__ Wc,
           float* __restrict__ out) {
    extern __shared__ float sm[];
    float* wzr  = sm;                 // [64][512]: rows 0-31 = z, 32-63 = r (h-halves)
    float* whs  = sm + 64 * 512;      // [32][512]
    float* hbuf = sm + 96 * 512;      // [2][512]
    float* rhbf = hbuf + 1024;        // [512]
    float* zbuf = rhbf + 512;         // [32]

    const int tid = threadIdx.x;
    unsigned rank; asm("mov.u32 %0, %%cluster_ctarank;" : "=r"(rank));
    const int b  = blockIdx.x / CLUSTER;
    const int j0 = (int)rank * RPC;
    const int w = tid >> 5, l = tid & 31;

    // load weights (h-half columns [512,1024)) : 32 rows x 128 float4 per gate
    for (int i = tid; i < 32 * 128; i += 512) {
        int r = i >> 7, q = (i & 127) * 4;
        *reinterpret_cast<float4*>(&wzr[r * 512 + q]) =
            *reinterpret_cast<const float4*>(Wz + (size_t)(j0 + r) * 1024 + 512 + q);
        *reinterpret_cast<float4*>(&wzr[(32 + r) * 512 + q]) =
            *reinterpret_cast<const float4*>(Wr + (size_t)(j0 + r) * 1024 + 512 + q);
        *reinterpret_cast<float4*>(&whs[r * 512 + q]) =
            *reinterpret_cast<const float4*>(Wh + (size_t)(j0 + r) * 1024 + 512 + q);
    }
    for (int i = tid; i < 1024; i += 512) hbuf[i] = 0.f;

    // stage1 roles: warps 0-7 -> z rows 4w..4w+3 ; warps 8-15 -> r rows
    const bool is_r = (w >= 8);
    const int lr0 = 4 * (w & 7);                 // local row base (0..28)
    // r-warp push addresses: lane pushes rows (lr0 + rsel, +1) to rank rk
    const int rk = l & 15, rsel = (l < 16) ? 0 : 2;
    uint32_t pushA = 0;
    if (is_r) pushA = dsmem_map(smem_u32(&rhbf[j0 + lr0 + rsel]), (unsigned)rk);
    // stage2 roles: rows 2w, 2w+1 ; lane pushes one row to rank rk
    const int s2row = 2 * w + ((l < 16) ? 0 : 1);
    const uint32_t hp0 = dsmem_map(smem_u32(&hbuf[0 * 512 + j0 + s2row]), (unsigned)rk);
    const uint32_t hp1 = dsmem_map(smem_u32(&hbuf[1 * 512 + j0 + s2row]), (unsigned)rk);

    cluster_sync();                               // weights + h0 visible everywhere

    int p = 0;
    for (int t = 0; t < S_LEN; t++) {
        const size_t gb = ((size_t)t * BATCH + b) * 1536;
        // prefetch gate-x pre-activations
        float gx1 = (l < 4) ? __ldcs(g_G + gb + (is_r ? 512 : 0) + j0 + lr0 + l) : 0.f;
        const float gx2 = __ldcs(g_G + gb + 1024 + j0 + s2row);

        // ---- stage 1: z|r over h ----
        float4 h4[4];
#pragma unroll
        for (int q = 0; q < 4; q++)
            h4[q] = *reinterpret_cast<const float4*>(&hbuf[p * 512 + q * 128 + l * 4]);
        float g0, g1, g2, g3;
        {
            float a[4];
#pragma unroll
            for (int i = 0; i < 4; i++) {
                const int row = lr0 + i + (is_r ? 32 : 0);
                float s = 0.f;
#pragma unroll
                for (int q = 0; q < 4; q++) {
                    float4 w4 = *reinterpret_cast<const float4*>(&wzr[row * 512 + q * 128 + l * 4]);
                    s = fmaf(w4.x, h4[q].x, s); s = fmaf(w4.y, h4[q].y, s);
                    s = fmaf(w4.z, h4[q].z, s); s = fmaf(w4.w, h4[q].w, s);
                }
#pragma unroll
                for (int d = 16; d; d >>= 1) s += __shfl_xor_sync(~0u, s, d);
                a[i] = s;
            }
            g0 = a[0]; g1 = a[1]; g2 = a[2]; g3 = a[3];
        }
        if (!is_r) {
            if (l < 4) {
                float s = (l == 0) ? g0 : (l == 1) ? g1 : (l == 2) ? g2 : g3;
                zbuf[lr0 + l] = 1.f / (1.f + expf(-(s + gx1)));
            }
        } else {
            float rh = 0.f;
            if (l < 4) {
                float s = (l == 0) ? g0 : (l == 1) ? g1 : (l == 2) ? g2 : g3;
                float r = 1.f / (1.f + expf(-(s + gx1)));
                rh = r * hbuf[p * 512 + j0 + lr0 + l];
            }
            const float rhA = __shfl_sync(~0u, rh, rsel);
            const float rhB = __shfl_sync(~0u, rh, rsel + 1);
            dsmem_st(pushA, rhA);
            dsmem_st(pushA + 4, rhB);
        }
        cluster_sync();

        // ---- stage 2: h' over r*h, update h ----
        float s2 = 0.f;
#pragma unroll
        for (int q = 0; q < 4; q++) {
            float4 r4 = *reinterpret_cast<const float4*>(&rhbf[q * 128 + l * 4]);
            float4 w4 = *reinterpret_cast<const float4*>(&whs[s2row * 512 + q * 128 + l * 4]);
            s2 = fmaf(w4.x, r4.x, s2); s2 = fmaf(w4.y, r4.y, s2);
            s2 = fmaf(w4.z, r4.z, s2); s2 = fmaf(w4.w, r4.w, s2);
        }
        // reduce over the 16 lanes that share s2row (xor 1,2,4,8 keeps halves separate)
#pragma unroll
        for (int d = 8; d; d >>= 1) s2 += __shfl_xor_sync(~0u, s2, d);
        s2 += __shfl_xor_sync(~0u, s2, 16);   // wrong half mixes rows! -- see fix below
        // NOTE: the xor-16 above would mix rows; undo by recomputing via halves:
        // (we instead rely on lanes only within their half: redo proper reduce)
        // -- replaced logic: s2 already fully reduced within half by d=8..1? No.
        // Correct approach below.
        (void)0;
        // recompute cleanly: sum within each 16-lane half only
        // (s2 was polluted; rebuild from scratch)
        float s2c = 0.f;
#pragma unroll
        for (int q = 0; q < 4; q++) {
            float4 r4 = *reinterpret_cast<const float4*>(&rhbf[q * 128 + l * 4]);
            float4 w4 = *reinterpret_cast<const float4*>(&whs[s2row * 512 + q * 128 + l * 4]);
            s2c = fmaf(w4.x, r4.x, s2c); s2c = fmaf(w4.y, r4.y, s2c);
            s2c = fmaf(w4.z, r4.z, s2c); s2c = fmaf(w4.w, r4.w, s2c);
        }
        // each half of the warp covers only k = q*128 + l*4 for its own lanes; but
        // both halves span the full 512 k-range, and rows differ between halves.
        // So reduction must stay within the half: xor 1,2,4,8 only... that sums 16
        // lanes covering HALF the k range. Fix: each half must cover full k.
        // Use k = q*128 + (l&15)*8 + (l>=16?4:0) so each 16-lane half covers all 512.
        s2 = 0.f;
#pragma unroll
        for (int q = 0; q < 4; q++) {
            const int kk = q * 128 + (l & 15) * 8 + ((l >= 16) ? 4 : 0);
            float4 r4 = *reinterpret_cast<const float4*>(&rhbf[kk]);
            float4 w4 = *reinterpret_cast<const float4*>(&whs[s2row * 512 + kk]);
            s2 = fmaf(w4.x, r4.x, s2); s2 = fmaf(w4.y, r4.y, s2);
            s2 = fmaf(w4.z, r4.z, s2); s2 = fmaf(w4.w, r4.w, s2);
        }
        // halves cover k ranges {(l&15)*8 .. +4} and {+4..+8}: union per half?  Each
        // half: 16 lanes * 4 floats * 4 q = 256 floats -> half the range. Need the
        // other half too: pair lanes l and l^16 hold complementary 4-float chunks of
        // the SAME row? No: rows differ between halves. Final correct scheme:
        // lane covers 32 floats of its own row: k = q*128 + (l&15)*8 .. +8.
        s2 = 0.f;
#pragma unroll
        for (int q = 0; q < 4; q++) {
            const int kk = q * 128 + (l & 15) * 8;
            float4 ra = *reinterpret_cast<const float4*>(&rhbf[kk]);
            float4 rb = *reinterpret_cast<const float4*>(&rhbf[kk + 4]);
            float4 wa = *reinterpret_cast<const float4*>(&whs[s2row * 512 + kk]);
            float4 wb = *reinterpret_cast<const float4*>(&whs[s2row * 512 + kk + 4]);
            s2 = fmaf(wa.x, ra.x, s2); s2 = fmaf(wa.y, ra.y, s2);
            s2 = fmaf(wa.z, ra.z, s2); s2 = fmaf(wa.w, ra.w, s2);
            s2 = fmaf(wb.x, rb.x, s2); s2 = fmaf(wb.y, rb.y, s2);
            s2 = fmaf(wb.z, rb.z, s2); s2 = fmaf(wb.w, rb.w, s2);
        }
#pragma unroll
        for (int d = 8; d; d >>= 1) s2 += __shfl_xor_sync(~0u, s2, d);
        // lanes within each 16-half now hold the full dot for s2row
        const float hc   = tanhf(s2 + gx2);
        const float z    = zbuf[s2row];
        const float hold = hbuf[p * 512 + j0 + s2row];
        const float hnew = hold + z * (hc - hold);
        dsmem_st(p ? hp0 : hp1, hnew);
        cluster_sync();
        p ^= 1;
    }

    // classifier (final h in hbuf[p==0]); rank 0 of each cluster writes out[b]
    if (rank == 0 && w < 10) {
        float s = 0.f;
        for (int k = l; k < DH; k += 32)
            s += hbuf[k] * Wc[(size_t)w * DH + k];
#pragma unroll
        for (int d = 16; d; d >>= 1) s += __shfl_xor_sync(~0u, s, d);
        if (l == 0) out[b * 10 + w] = s;
    }
}

extern "C" void kernel_launch(void* const* d_in, const int* in_sizes, int n_in,
                              void* d_out, int out_size) {
    const float* x   = (const float*)d_in[0];
    const float* Wlm = (const float*)d_in[1];
    const float* Wz  = (const float*)d_in[2];
    const float* Wr  = (const float*)d_in[3];
    const float* Wh  = (const float*)d_in[4];
    const float* Wc  = (const float*)d_in[5];
    float* out = (float*)d_out;

    const int smem_bytes = GRU_SMEM_FLOATS * 4;
    cudaFuncSetAttribute(gru_kernel, cudaFuncAttributeNonPortableClusterSizeAllowed, 1);
    cudaFuncSetAttribute(gru_kernel, cudaFuncAttributeMaxDynamicSharedMemorySize, smem_bytes);

    gemm1_kernel<<<dim3(8, 256), 256>>>(x, Wlm);
    gemm2_kernel<<<dim3(24, 256), 256>>>(Wz, Wr, Wh);
    gru_kernel<<<BATCH * CLUSTER, 512, smem_bytes>>>(Wz, Wr, Wh, Wc, out);
}

// round 7
// speedup vs baseline: 2.4030x; 1.2149x over previous
#include <cuda_runtime.h>
#include <cstdint>
#include <cstddef>

#define S_LEN 4096
#define BATCH 8
#define DH    512
#define DIN   2048
#define M_TOT (S_LEN * BATCH)
#define CLUSTER 16
#define RPC   32

__device__ float g_seq[(size_t)M_TOT * DH];
__device__ float g_G[(size_t)M_TOT * 3 * DH];

// ================= GEMM1: seq = x @ Wlm^T (M=32768,N=512,K=2048) ===============
__global__ __launch_bounds__(256) void gemm1_kernel(const float* __restrict__ x,
                                                    const float* __restrict__ Wlm) {
    __shared__ float As[16][132], Bs[16][132];
    const int m0 = blockIdx.y * 128, n0 = blockIdx.x * 128, tid = threadIdx.x;
    const int tx = tid & 15, ty = tid >> 4;
    float acc[8][8] = {};
    for (int k0 = 0; k0 < DIN; k0 += 16) {
#pragma unroll
        for (int i = 0; i < 2; i++) {                 // A tile, transposed store
            int f = tid * 2 + i, m = f >> 2, kq = f & 3;
            int gm = m0 + m, b = gm & 7, t = gm >> 3;
            float4 v = *reinterpret_cast<const float4*>(x + ((size_t)b * S_LEN + t) * DIN + k0 + kq * 4);
            As[kq*4+0][m] = v.x; As[kq*4+1][m] = v.y; As[kq*4+2][m] = v.z; As[kq*4+3][m] = v.w;
        }
#pragma unroll
        for (int i = 0; i < 2; i++) {                 // B tile
            int f = tid * 2 + i, n = f >> 2, kq = f & 3;
            float4 v = *reinterpret_cast<const float4*>(Wlm + (size_t)(n0 + n) * DIN + k0 + kq * 4);
            Bs[kq*4+0][n] = v.x; Bs[kq*4+1][n] = v.y; Bs[kq*4+2][n] = v.z; Bs[kq*4+3][n] = v.w;
        }
        __syncthreads();
#pragma unroll
        for (int kk = 0; kk < 16; kk++) {
            float4 a0 = *(const float4*)&As[kk][ty*8], a1 = *(const float4*)&As[kk][ty*8+4];
            float4 b0 = *(const float4*)&Bs[kk][tx*4], b1 = *(const float4*)&Bs[kk][64+tx*4];
            float a[8] = {a0.x,a0.y,a0.z,a0.w,a1.x,a1.y,a1.z,a1.w};
            float bb[8] = {b0.x,b0.y,b0.z,b0.w,b1.x,b1.y,b1.z,b1.w};
#pragma unroll
            for (int i = 0; i < 8; i++)
#pragma unroll
                for (int j = 0; j < 8; j++) acc[i][j] = fmaf(a[i], bb[j], acc[i][j]);
        }
        __syncthreads();
    }
#pragma unroll
    for (int i = 0; i < 8; i++) {
        size_t row = (size_t)(m0 + ty * 8 + i) * DH;
        *(float4*)&g_seq[row + n0 + tx*4]      = make_float4(acc[i][0],acc[i][1],acc[i][2],acc[i][3]);
        *(float4*)&g_seq[row + n0 + 64 + tx*4] = make_float4(acc[i][4],acc[i][5],acc[i][6],acc[i][7]);
    }
}

// ============ GEMM2: G = seq @ [Wzx|Wrx|Whx]^T (M=32768,N=1536,K=512) ==========
__global__ __launch_bounds__(256) void gemm2_kernel(const float* __restrict__ Wz,
                                                    const float* __restrict__ Wr,
                                                    const float* __restrict__ Wh) {
    __shared__ float As[16][132], Bs[16][132];
    const int m0 = blockIdx.y * 128, n0 = blockIdx.x * 128, tid = threadIdx.x;
    const int tx = tid & 15, ty = tid >> 4;
    const float* base = (n0 < 512) ? Wz : (n0 < 1024) ? Wr : Wh;
    const int br0 = n0 & 511;
    float acc[8][8] = {};
    for (int k0 = 0; k0 < DH; k0 += 16) {
#pragma unroll
        for (int i = 0; i < 2; i++) {
            int f = tid * 2 + i, m = f >> 2, kq = f & 3;
            float4 v = *reinterpret_cast<const float4*>(g_seq + (size_t)(m0 + m) * DH + k0 + kq * 4);
            As[kq*4+0][m] = v.x; As[kq*4+1][m] = v.y; As[kq*4+2][m] = v.z; As[kq*4+3][m] = v.w;
        }
#pragma unroll
        for (int i = 0; i < 2; i++) {                 // x-half cols [0,512)
            int f = tid * 2 + i, n = f >> 2, kq = f & 3;
            float4 v = *reinterpret_cast<const float4*>(base + (size_t)(br0 + n) * 1024 + k0 + kq * 4);
            Bs[kq*4+0][n] = v.x; Bs[kq*4+1][n] = v.y; Bs[kq*4+2][n] = v.z; Bs[kq*4+3][n] = v.w;
        }
        __syncthreads();
#pragma unroll
        for (int kk = 0; kk < 16; kk++) {
            float4 a0 = *(const float4*)&As[kk][ty*8], a1 = *(const float4*)&As[kk][ty*8+4];
            float4 b0 = *(const float4*)&Bs[kk][tx*4], b1 = *(const float4*)&Bs[kk][64+tx*4];
            float a[8] = {a0.x,a0.y,a0.z,a0.w,a1.x,a1.y,a1.z,a1.w};
            float bb[8] = {b0.x,b0.y,b0.z,b0.w,b1.x,b1.y,b1.z,b1.w};
#pragma unroll
            for (int i = 0; i < 8; i++)
#pragma unroll
                for (int j = 0; j < 8; j++) acc[i][j] = fmaf(a[i], bb[j], acc[i][j]);
        }
        __syncthreads();
    }
#pragma unroll
    for (int i = 0; i < 8; i++) {
        size_t row = (size_t)(m0 + ty * 8 + i) * 1536;
        *(float4*)&g_G[row + n0 + tx*4]      = make_float4(acc[i][0],acc[i][1],acc[i][2],acc[i][3]);
        *(float4*)&g_G[row + n0 + 64 + tx*4] = make_float4(acc[i][4],acc[i][5],acc[i][6],acc[i][7]);
    }
}

// ================= cluster / mbarrier helpers =================
__device__ __forceinline__ uint32_t smem_u32(const void* p) {
    return (uint32_t)__cvta_generic_to_shared(p);
}
__device__ __forceinline__ uint32_t dsmem_map(uint32_t a, unsigned r) {
    uint32_t x; asm("mapa.shared::cluster.u32 %0, %1, %2;" : "=r"(x) : "r"(a), "r"(r)); return x;
}
__device__ __forceinline__ void dsmem_st64(uint32_t a, float x, float y) {
    unsigned long long v = ((unsigned long long)__float_as_uint(y) << 32) | __float_as_uint(x);
    asm volatile("st.shared::cluster.b64 [%0], %1;" :: "r"(a), "l"(v) : "memory");
}
__device__ __forceinline__ void cl_arrive() {
    asm volatile("barrier.cluster.arrive.aligned;" ::: "memory");
}
__device__ __forceinline__ void cl_wait() {
    asm volatile("barrier.cluster.wait.aligned;" ::: "memory");
}
__device__ __forceinline__ void mbar_init(uint32_t a, uint32_t cnt) {
    asm volatile("mbarrier.init.shared.b64 [%0], %1;" :: "r"(a), "r"(cnt) : "memory");
}
__device__ __forceinline__ void mbar_arrive(uint32_t a) {
    asm volatile("mbarrier.arrive.shared.b64 _, [%0];" :: "r"(a) : "memory");
}
__device__ __forceinline__ void mbar_wait(uint32_t a, uint32_t parity) {
    uint32_t done;
    asm volatile("{\n\t.reg .pred p;\n\t"
                 "mbarrier.try_wait.parity.shared.b64 p, [%1], %2;\n\t"
                 "selp.b32 %0, 1, 0, p;\n\t}"
                 : "=r"(done) : "r"(a), "r"(parity) : "memory");
    while (!done) {
        asm volatile("{\n\t.reg .pred p;\n\t"
                     "mbarrier.try_wait.parity.shared.b64 p, [%1], %2;\n\t"
                     "selp.b32 %0, 1, 0, p;\n\t}"
                     : "=r"(done) : "r"(a), "r"(parity) : "memory");
    }
}
__device__ __forceinline__ float sigmoidf_(float v) { return 1.f / (1.f + __expf(-v)); }

// ====== GRU: 8 clusters x 16 CTAs x 512 thr; smem weights; z in sync shadow ====
__global__ void __cluster_dims__(CLUSTER, 1, 1) __launch_bounds__(512, 1)
gru_kernel(const float* __restrict__ Wz, const float* __restrict__ Wr,
           const float* __restrict__ Wh, const float* __restrict__ Wc,
           float* __restrict__ out) {
    extern __shared__ float sm[];
    float* wAll = sm;                    // [96][512]: r rows 0-31, z 32-63, h 64-95
    float* hbuf = sm + 96 * 512;         // [2][512]
    float* rhbf = hbuf + 1024;           // [512]
    float* zbuf = rhbf + 512;            // [32]
    uint32_t zmbar = smem_u32(zbuf + 32);  // 8B mbarrier (8-byte aligned)

    const int tid = threadIdx.x;
    unsigned rank; asm("mov.u32 %0, %%cluster_ctarank;" : "=r"(rank));
    const int b  = blockIdx.x / CLUSTER;
    const int j0 = (int)rank * RPC;
    const int w = tid >> 5, l = tid & 31;

    for (int i = tid; i < 32 * 128; i += 512) {       // weights (h-half cols)
        int r = i >> 7, q = (i & 127) * 4;
        *(float4*)&wAll[r * 512 + q]        = *(const float4*)(Wr + (size_t)(j0 + r) * 1024 + 512 + q);
        *(float4*)&wAll[(32 + r) * 512 + q] = *(const float4*)(Wz + (size_t)(j0 + r) * 1024 + 512 + q);
        *(float4*)&wAll[(64 + r) * 512 + q] = *(const float4*)(Wh + (size_t)(j0 + r) * 1024 + 512 + q);
    }
    for (int i = tid; i < 1024; i += 512) hbuf[i] = 0.f;
    if (tid == 0) mbar_init(zmbar, 256);
    __syncthreads();

    const bool isR = (w < 8);
    const int lw  = isR ? w : (w - 8);
    const int lr0 = lw * 4;
    const int half = l >> 4;
    const int r0 = lr0 + half * 2;                    // this lane's 2 local rows
    const unsigned rk = (unsigned)(l & 15);
    const uint32_t rh_push = dsmem_map(smem_u32(&rhbf[j0 + r0]), rk);
    const uint32_t h_push0 = dsmem_map(smem_u32(&hbuf[0 * 512 + j0 + r0]), rk);
    const uint32_t h_push1 = dsmem_map(smem_u32(&hbuf[1 * 512 + j0 + r0]), rk);

    const size_t gx_a = (isR ? 512 : 0) + j0 + r0;    // r or z column offset
    const size_t gx_h = 1024 + j0 + r0;

    cl_arrive(); cl_wait();                            // weights + h0 visible

    // preload gate-x pre-acts for t=0
    float ga0 = __ldcs(g_G + (size_t)b * 1536 + gx_a);
    float ga1 = __ldcs(g_G + (size_t)b * 1536 + gx_a + 1);
    float gh0 = 0.f, gh1 = 0.f;
    if (isR) {
        gh0 = __ldcs(g_G + (size_t)b * 1536 + gx_h);
        gh1 = __ldcs(g_G + (size_t)b * 1536 + gx_h + 1);
    }

    int p = 0;
    uint32_t zph = 0;
    for (int t = 0; t < S_LEN; t++) {
        const int tn = (t + 1 < S_LEN) ? t + 1 : t;
        const size_t gbn = ((size_t)tn * 8 + b) * 1536;
        float gna0 = 0.f, gna1 = 0.f, gnh0 = 0.f, gnh1 = 0.f;

        if (isR) {
            // ---- r pre-acts (4 rows), push r*h ----
            float4 h4[4];
#pragma unroll
            for (int q = 0; q < 4; q++) h4[q] = *(const float4*)&hbuf[p * 512 + q * 128 + l * 4];
            float a[4];
#pragma unroll
            for (int i = 0; i < 4; i++) {
                float s = 0.f;
#pragma unroll
                for (int q = 0; q < 4; q++) {
                    float4 w4 = *(const float4*)&wAll[(lr0 + i) * 512 + q * 128 + l * 4];
                    s = fmaf(w4.x, h4[q].x, s); s = fmaf(w4.y, h4[q].y, s);
                    s = fmaf(w4.z, h4[q].z, s); s = fmaf(w4.w, h4[q].w, s);
                }
#pragma unroll
                for (int d = 16; d; d >>= 1) s += __shfl_xor_sync(~0u, s, d);
                a[i] = s;
            }
            float rv0 = sigmoidf_(a[half * 2]     + ga0);
            float rv1 = sigmoidf_(a[half * 2 + 1] + ga1);
            float rh0 = rv0 * hbuf[p * 512 + j0 + r0];
            float rh1 = rv1 * hbuf[p * 512 + j0 + r0 + 1];
            dsmem_st64(rh_push, rh0, rh1);
            gna0 = __ldcs(g_G + gbn + gx_a);           // prefetch t+1
            gna1 = __ldcs(g_G + gbn + gx_a + 1);
            gnh0 = __ldcs(g_G + gbn + gx_h);
            gnh1 = __ldcs(g_G + gbn + gx_h + 1);
        }
        cl_arrive();
        if (!isR) {
            // ---- z pre-acts in the sync shadow ----
            float4 h4[4];
#pragma unroll
            for (int q = 0; q < 4; q++) h4[q] = *(const float4*)&hbuf[p * 512 + q * 128 + l * 4];
            float a[4];
#pragma unroll
            for (int i = 0; i < 4; i++) {
                float s = 0.f;
#pragma unroll
                for (int q = 0; q < 4; q++) {
                    float4 w4 = *(const float4*)&wAll[(32 + lr0 + i) * 512 + q * 128 + l * 4];
                    s = fmaf(w4.x, h4[q].x, s); s = fmaf(w4.y, h4[q].y, s);
                    s = fmaf(w4.z, h4[q].z, s); s = fmaf(w4.w, h4[q].w, s);
                }
#pragma unroll
                for (int d = 16; d; d >>= 1) s += __shfl_xor_sync(~0u, s, d);
                a[i] = s;
            }
            if (rk == 0) {
                zbuf[r0]     = sigmoidf_(a[half * 2]     + ga0);
                zbuf[r0 + 1] = sigmoidf_(a[half * 2 + 1] + ga1);
            }
            mbar_arrive(zmbar);                        // release zbuf writes
            gna0 = __ldcs(g_G + gbn + gx_a);
            gna1 = __ldcs(g_G + gbn + gx_a + 1);
        }
        cl_wait();                                     // r*h complete everywhere
        if (isR) {
            // ---- h' (4 rows) over r*h, update h ----
            float4 r4[4];
#pragma unroll
            for (int q = 0; q < 4; q++) r4[q] = *(const float4*)&rhbf[q * 128 + l * 4];
            float a[4];
#pragma unroll
            for (int i = 0; i < 4; i++) {
                float s = 0.f;
#pragma unroll
                for (int q = 0; q < 4; q++) {
                    float4 w4 = *(const float4*)&wAll[(64 + lr0 + i) * 512 + q * 128 + l * 4];
                    s = fmaf(w4.x, r4[q].x, s); s = fmaf(w4.y, r4[q].y, s);
                    s = fmaf(w4.z, r4[q].z, s); s = fmaf(w4.w, r4[q].w, s);
                }
#pragma unroll
                for (int d = 16; d; d >>= 1) s += __shfl_xor_sync(~0u, s, d);
                a[i] = s;
            }
            float hc0 = tanhf(a[half * 2]     + gh0);
            float hc1 = tanhf(a[half * 2 + 1] + gh1);
            mbar_wait(zmbar, zph);                     // acquire zbuf
            float z0 = zbuf[r0], z1 = zbuf[r0 + 1];
            float ho0 = hbuf[p * 512 + j0 + r0], ho1 = hbuf[p * 512 + j0 + r0 + 1];
            float hn0 = ho0 + z0 * (hc0 - ho0);
            float hn1 = ho1 + z1 * (hc1 - ho1);
            dsmem_st64(p ? h_push0 : h_push1, hn0, hn1);
        } else {
            mbar_wait(zmbar, zph);                     // keep parity in lockstep
        }
        cl_arrive();
        cl_wait();                                     // h(t+1) complete everywhere
        ga0 = gna0; ga1 = gna1; gh0 = gnh0; gh1 = gnh1;
        zph ^= 1;
        p ^= 1;
    }

    // classifier: final h in hbuf[0]; rank 0 of each cluster writes out[b][10]
    if (rank == 0 && w < 10) {
        float s = 0.f;
        for (int k = l; k < DH; k += 32)
            s += hbuf[k] * Wc[(size_t)w * DH + k];
#pragma unroll
        for (int d = 16; d; d >>= 1) s += __shfl_xor_sync(~0u, s, d);
        if (l == 0) out[b * 10 + w] = s;
    }
}

extern "C" void kernel_launch(void* const* d_in, const int* in_sizes, int n_in,
                              void* d_out, int out_size) {
    const float* x   = (const float*)d_in[0];
    const float* Wlm = (const float*)d_in[1];
    const float* Wz  = (const float*)d_in[2];
    const float* Wr  = (const float*)d_in[3];
    const float* Wh  = (const float*)d_in[4];
    const float* Wc  = (const float*)d_in[5];
    float* out = (float*)d_out;

    const int smem_bytes = (96 * 512 + 2 * 512 + 512 + 32 + 2) * 4;  // +8B mbarrier
    cudaFuncSetAttribute(gru_kernel, cudaFuncAttributeNonPortableClusterSizeAllowed, 1);
    cudaFuncSetAttribute(gru_kernel, cudaFuncAttributeMaxDynamicSharedMemorySize, smem_bytes);

    gemm1_kernel<<<dim3(4, 256), 256>>>(x, Wlm);
    gemm2_kernel<<<dim3(12, 256), 256>>>(Wz, Wr, Wh);
    gru_kernel<<<BATCH * CLUSTER, 512, smem_bytes>>>(Wz, Wr, Wh, Wc, out);
}

// round 8
// speedup vs baseline: 3.3365x; 1.3885x over previous
#include <cuda_runtime.h>
#include <cstdint>
#include <cstddef>

#define S_LEN 4096
#define BATCH 8
#define DH    512
#define DIN   2048
#define M_TOT (S_LEN * BATCH)
#define CLUSTER 16
#define RPC   32

__device__ float g_seq[(size_t)M_TOT * DH];
__device__ float g_G[(size_t)M_TOT * 3 * DH];

// ================= GEMM1: seq = x @ Wlm^T (M=32768,N=512,K=2048) ===============
__global__ __launch_bounds__(256) void gemm1_kernel(const float* __restrict__ x,
                                                    const float* __restrict__ Wlm) {
    __shared__ float As[16][132], Bs[16][132];
    const int m0 = blockIdx.y * 128, n0 = blockIdx.x * 128, tid = threadIdx.x;
    const int tx = tid & 15, ty = tid >> 4;
    float acc[8][8] = {};
    for (int k0 = 0; k0 < DIN; k0 += 16) {
#pragma unroll
        for (int i = 0; i < 2; i++) {
            int f = tid * 2 + i, m = f >> 2, kq = f & 3;
            int gm = m0 + m, b = gm & 7, t = gm >> 3;
            float4 v = *reinterpret_cast<const float4*>(x + ((size_t)b * S_LEN + t) * DIN + k0 + kq * 4);
            As[kq*4+0][m] = v.x; As[kq*4+1][m] = v.y; As[kq*4+2][m] = v.z; As[kq*4+3][m] = v.w;
        }
#pragma unroll
        for (int i = 0; i < 2; i++) {
            int f = tid * 2 + i, n = f >> 2, kq = f & 3;
            float4 v = *reinterpret_cast<const float4*>(Wlm + (size_t)(n0 + n) * DIN + k0 + kq * 4);
            Bs[kq*4+0][n] = v.x; Bs[kq*4+1][n] = v.y; Bs[kq*4+2][n] = v.z; Bs[kq*4+3][n] = v.w;
        }
        __syncthreads();
#pragma unroll
        for (int kk = 0; kk < 16; kk++) {
            float4 a0 = *(const float4*)&As[kk][ty*8], a1 = *(const float4*)&As[kk][ty*8+4];
            float4 b0 = *(const float4*)&Bs[kk][tx*4], b1 = *(const float4*)&Bs[kk][64+tx*4];
            float a[8] = {a0.x,a0.y,a0.z,a0.w,a1.x,a1.y,a1.z,a1.w};
            float bb[8] = {b0.x,b0.y,b0.z,b0.w,b1.x,b1.y,b1.z,b1.w};
#pragma unroll
            for (int i = 0; i < 8; i++)
#pragma unroll
                for (int j = 0; j < 8; j++) acc[i][j] = fmaf(a[i], bb[j], acc[i][j]);
        }
        __syncthreads();
    }
#pragma unroll
    for (int i = 0; i < 8; i++) {
        size_t row = (size_t)(m0 + ty * 8 + i) * DH;
        *(float4*)&g_seq[row + n0 + tx*4]      = make_float4(acc[i][0],acc[i][1],acc[i][2],acc[i][3]);
        *(float4*)&g_seq[row + n0 + 64 + tx*4] = make_float4(acc[i][4],acc[i][5],acc[i][6],acc[i][7]);
    }
}

// ============ GEMM2: G = seq @ [Wzx|Wrx|Whx]^T (M=32768,N=1536,K=512) ==========
__global__ __launch_bounds__(256) void gemm2_kernel(const float* __restrict__ Wz,
                                                    const float* __restrict__ Wr,
                                                    const float* __restrict__ Wh) {
    __shared__ float As[16][132], Bs[16][132];
    const int m0 = blockIdx.y * 128, n0 = blockIdx.x * 128, tid = threadIdx.x;
    const int tx = tid & 15, ty = tid >> 4;
    const float* base = (n0 < 512) ? Wz : (n0 < 1024) ? Wr : Wh;
    const int br0 = n0 & 511;
    float acc[8][8] = {};
    for (int k0 = 0; k0 < DH; k0 += 16) {
#pragma unroll
        for (int i = 0; i < 2; i++) {
            int f = tid * 2 + i, m = f >> 2, kq = f & 3;
            float4 v = *reinterpret_cast<const float4*>(g_seq + (size_t)(m0 + m) * DH + k0 + kq * 4);
            As[kq*4+0][m] = v.x; As[kq*4+1][m] = v.y; As[kq*4+2][m] = v.z; As[kq*4+3][m] = v.w;
        }
#pragma unroll
        for (int i = 0; i < 2; i++) {
            int f = tid * 2 + i, n = f >> 2, kq = f & 3;
            float4 v = *reinterpret_cast<const float4*>(base + (size_t)(br0 + n) * 1024 + k0 + kq * 4);
            Bs[kq*4+0][n] = v.x; Bs[kq*4+1][n] = v.y; Bs[kq*4+2][n] = v.z; Bs[kq*4+3][n] = v.w;
        }
        __syncthreads();
#pragma unroll
        for (int kk = 0; kk < 16; kk++) {
            float4 a0 = *(const float4*)&As[kk][ty*8], a1 = *(const float4*)&As[kk][ty*8+4];
            float4 b0 = *(const float4*)&Bs[kk][tx*4], b1 = *(const float4*)&Bs[kk][64+tx*4];
            float a[8] = {a0.x,a0.y,a0.z,a0.w,a1.x,a1.y,a1.z,a1.w};
            float bb[8] = {b0.x,b0.y,b0.z,b0.w,b1.x,b1.y,b1.z,b1.w};
#pragma unroll
            for (int i = 0; i < 8; i++)
#pragma unroll
                for (int j = 0; j < 8; j++) acc[i][j] = fmaf(a[i], bb[j], acc[i][j]);
        }
        __syncthreads();
    }
#pragma unroll
    for (int i = 0; i < 8; i++) {
        size_t row = (size_t)(m0 + ty * 8 + i) * 1536;
        *(float4*)&g_G[row + n0 + tx*4]      = make_float4(acc[i][0],acc[i][1],acc[i][2],acc[i][3]);
        *(float4*)&g_G[row + n0 + 64 + tx*4] = make_float4(acc[i][4],acc[i][5],acc[i][6],acc[i][7]);
    }
}

// ================= helpers =================
__device__ __forceinline__ uint32_t smem_u32(const void* p) {
    return (uint32_t)__cvta_generic_to_shared(p);
}
__device__ __forceinline__ uint32_t dsmem_map(uint32_t a, unsigned r) {
    uint32_t x; asm("mapa.shared::cluster.u32 %0, %1, %2;" : "=r"(x) : "r"(a), "r"(r)); return x;
}
// remote smem store with tx credit on the destination CTA's mbarrier
__device__ __forceinline__ void st_async64(uint32_t addr, uint32_t mbar, float x, float y) {
    unsigned long long v = ((unsigned long long)__float_as_uint(y) << 32) | __float_as_uint(x);
    asm volatile("st.async.shared::cluster.mbarrier::complete_tx::bytes.u64 [%0], %1, [%2];"
                 :: "r"(addr), "l"(v), "r"(mbar) : "memory");
}
__device__ __forceinline__ void mbar_init(uint32_t a, uint32_t cnt) {
    asm volatile("mbarrier.init.shared.b64 [%0], %1;" :: "r"(a), "r"(cnt) : "memory");
}
__device__ __forceinline__ void mbar_arrive(uint32_t a) {
    asm volatile("mbarrier.arrive.shared.b64 _, [%0];" :: "r"(a) : "memory");
}
__device__ __forceinline__ void mbar_expect_tx(uint32_t a, uint32_t tx) {
    asm volatile("mbarrier.arrive.expect_tx.shared.b64 _, [%0], %1;" :: "r"(a), "r"(tx) : "memory");
}
__device__ __forceinline__ void mbar_wait(uint32_t a, uint32_t parity) {
    uint32_t done;
    asm volatile("{\n\t.reg .pred p;\n\t"
                 "mbarrier.try_wait.parity.shared.b64 p, [%1], %2;\n\t"
                 "selp.b32 %0, 1, 0, p;\n\t}"
                 : "=r"(done) : "r"(a), "r"(parity) : "memory");
    while (!done) {
        asm volatile("{\n\t.reg .pred p;\n\t"
                     "mbarrier.try_wait.parity.shared.b64 p, [%1], %2;\n\t"
                     "selp.b32 %0, 1, 0, p;\n\t}"
                     : "=r"(done) : "r"(a), "r"(parity) : "memory");
    }
}
__device__ __forceinline__ void cl_sync() {
    asm volatile("barrier.cluster.arrive.aligned;" ::: "memory");
    asm volatile("barrier.cluster.wait.aligned;"   ::: "memory");
}
__device__ __forceinline__ float sigmoidf_(float v) { return 1.f / (1.f + __expf(-v)); }

// ====== GRU: 8 clusters x 16 CTAs x 512 thr; tx-mbarrier sync, no bulk barriers =
__global__ void __cluster_dims__(CLUSTER, 1, 1) __launch_bounds__(512, 1)
gru_kernel(const float* __restrict__ Wz, const float* __restrict__ Wr,
           const float* __restrict__ Wh, const float* __restrict__ Wc,
           float* __restrict__ out) {
    extern __shared__ float sm[];
    float* wAll = sm;                    // [96][512]: r 0-31, z 32-63, h 64-95
    float* hbuf = sm + 96 * 512;         // [2][512]
    float* rhbf = hbuf + 1024;           // [2][512]
    float* zbuf = rhbf + 1024;           // [32]
    uint32_t mb_rh = smem_u32(zbuf + 32);        // 8B
    uint32_t mb_h  = mb_rh + 8;
    uint32_t mb_z  = mb_rh + 16;

    const int tid = threadIdx.x;
    unsigned rank; asm("mov.u32 %0, %%cluster_ctarank;" : "=r"(rank));
    const int b  = blockIdx.x / CLUSTER;
    const int j0 = (int)rank * RPC;
    const int w = tid >> 5, l = tid & 31;

    for (int i = tid; i < 32 * 128; i += 512) {
        int r = i >> 7, q = (i & 127) * 4;
        *(float4*)&wAll[r * 512 + q]        = *(const float4*)(Wr + (size_t)(j0 + r) * 1024 + 512 + q);
        *(float4*)&wAll[(32 + r) * 512 + q] = *(const float4*)(Wz + (size_t)(j0 + r) * 1024 + 512 + q);
        *(float4*)&wAll[(64 + r) * 512 + q] = *(const float4*)(Wh + (size_t)(j0 + r) * 1024 + 512 + q);
    }
    for (int i = tid; i < 1024; i += 512) hbuf[i] = 0.f;
    if (tid == 0) { mbar_init(mb_rh, 1); mbar_init(mb_h, 1); mbar_init(mb_z, 256); }
    __syncthreads();

    const bool isR = (w < 8);
    const int lw  = isR ? w : (w - 8);
    const int lr0 = lw * 4;
    const int half = l >> 4;
    const int r0 = lr0 + half * 2;
    const unsigned rk = (unsigned)(l & 15);
    // remote data + barrier addresses for this lane's destination rank rk
    const uint32_t rh_p0 = dsmem_map(smem_u32(&rhbf[0 * 512 + j0 + r0]), rk);
    const uint32_t rh_p1 = dsmem_map(smem_u32(&rhbf[1 * 512 + j0 + r0]), rk);
    const uint32_t h_p0  = dsmem_map(smem_u32(&hbuf[0 * 512 + j0 + r0]), rk);
    const uint32_t h_p1  = dsmem_map(smem_u32(&hbuf[1 * 512 + j0 + r0]), rk);
    const uint32_t mrh_r = dsmem_map(mb_rh, rk);
    const uint32_t mh_r  = dsmem_map(mb_h, rk);

    const size_t gx_a = (isR ? 512 : 0) + j0 + r0;
    const size_t gx_h = 1024 + j0 + r0;

    cl_sync();                                    // mbars + h0 + weights live

    float ga0 = __ldcs(g_G + (size_t)b * 1536 + gx_a);
    float ga1 = __ldcs(g_G + (size_t)b * 1536 + gx_a + 1);
    float gh0 = 0.f, gh1 = 0.f;
    if (isR) {
        gh0 = __ldcs(g_G + (size_t)b * 1536 + gx_h);
        gh1 = __ldcs(g_G + (size_t)b * 1536 + gx_h + 1);
    }

    int p = 0;
    uint32_t ph = 0;
    for (int t = 0; t < S_LEN; t++) {
        if (tid == 0) {                            // arm this phase's tx budgets
            mbar_expect_tx(mb_rh, 2048);
            mbar_expect_tx(mb_h, 2048);
        }
        const int tn = (t + 1 < S_LEN) ? t + 1 : t;
        const size_t gbn = ((size_t)tn * 8 + b) * 1536;
        float gna0, gna1, gnh0 = 0.f, gnh1 = 0.f;
        const int rb = t & 1;                      // rhbf parity

        if (isR) {
            // ---- r pre-acts, push r*h (self-signaling) ----
            float4 h4[4];
#pragma unroll
            for (int q = 0; q < 4; q++) h4[q] = *(const float4*)&hbuf[p * 512 + q * 128 + l * 4];
            float a[4];
#pragma unroll
            for (int i = 0; i < 4; i++) {
                float s = 0.f;
#pragma unroll
                for (int q = 0; q < 4; q++) {
                    float4 w4 = *(const float4*)&wAll[(lr0 + i) * 512 + q * 128 + l * 4];
                    s = fmaf(w4.x, h4[q].x, s); s = fmaf(w4.y, h4[q].y, s);
                    s = fmaf(w4.z, h4[q].z, s); s = fmaf(w4.w, h4[q].w, s);
                }
#pragma unroll
                for (int d = 16; d; d >>= 1) s += __shfl_xor_sync(~0u, s, d);
                a[i] = s;
            }
            float rv0 = sigmoidf_(a[half * 2]     + ga0);
            float rv1 = sigmoidf_(a[half * 2 + 1] + ga1);
            float rh0 = rv0 * hbuf[p * 512 + j0 + r0];
            float rh1 = rv1 * hbuf[p * 512 + j0 + r0 + 1];
            st_async64(rb ? rh_p1 : rh_p0, mrh_r, rh0, rh1);
            gna0 = __ldcs(g_G + gbn + gx_a);
            gna1 = __ldcs(g_G + gbn + gx_a + 1);
            gnh0 = __ldcs(g_G + gbn + gx_h);
            gnh1 = __ldcs(g_G + gbn + gx_h + 1);

            mbar_wait(mb_rh, ph);                  // full r*h resident locally
            // ---- h' over r*h ----
            float4 r4[4];
#pragma unroll
            for (int q = 0; q < 4; q++) r4[q] = *(const float4*)&rhbf[rb * 512 + q * 128 + l * 4];
            float c[4];
#pragma unroll
            for (int i = 0; i < 4; i++) {
                float s = 0.f;
#pragma unroll
                for (int q = 0; q < 4; q++) {
                    float4 w4 = *(const float4*)&wAll[(64 + lr0 + i) * 512 + q * 128 + l * 4];
                    s = fmaf(w4.x, r4[q].x, s); s = fmaf(w4.y, r4[q].y, s);
                    s = fmaf(w4.z, r4[q].z, s); s = fmaf(w4.w, r4[q].w, s);
                }
#pragma unroll
                for (int d = 16; d; d >>= 1) s += __shfl_xor_sync(~0u, s, d);
                c[i] = s;
            }
            float hc0 = tanhf(c[half * 2]     + gh0);
            float hc1 = tanhf(c[half * 2 + 1] + gh1);
            mbar_wait(mb_z, ph);                   // z ready (local)
            float z0 = zbuf[r0], z1 = zbuf[r0 + 1];
            float ho0 = hbuf[p * 512 + j0 + r0], ho1 = hbuf[p * 512 + j0 + r0 + 1];
            float hn0 = ho0 + z0 * (hc0 - ho0);
            float hn1 = ho1 + z1 * (hc1 - ho1);
            st_async64(p ? h_p0 : h_p1, mh_r, hn0, hn1);
        } else {
            // ---- z pre-acts (concurrent with r-warps) ----
            float4 h4[4];
#pragma unroll
            for (int q = 0; q < 4; q++) h4[q] = *(const float4*)&hbuf[p * 512 + q * 128 + l * 4];
            float a[4];
#pragma unroll
            for (int i = 0; i < 4; i++) {
                float s = 0.f;
#pragma unroll
                for (int q = 0; q < 4; q++) {
                    float4 w4 = *(const float4*)&wAll[(32 + lr0 + i) * 512 + q * 128 + l * 4];
                    s = fmaf(w4.x, h4[q].x, s); s = fmaf(w4.y, h4[q].y, s);
                    s = fmaf(w4.z, h4[q].z, s); s = fmaf(w4.w, h4[q].w, s);
                }
#pragma unroll
                for (int d = 16; d; d >>= 1) s += __shfl_xor_sync(~0u, s, d);
                a[i] = s;
            }
            if (rk == 0) {
                zbuf[r0]     = sigmoidf_(a[half * 2]     + ga0);
                zbuf[r0 + 1] = sigmoidf_(a[half * 2 + 1] + ga1);
            }
            mbar_arrive(mb_z);                     // release zbuf
            gna0 = __ldcs(g_G + gbn + gx_a);
            gna1 = __ldcs(g_G + gbn + gx_a + 1);
            mbar_wait(mb_z, ph);                   // keep z-parity in lockstep
        }
        mbar_wait(mb_h, ph);                       // h(t+1) resident locally
        ga0 = gna0; ga1 = gna1; gh0 = gnh0; gh1 = gnh1;
        ph ^= 1; p ^= 1;
    }

    // classifier: final h in hbuf[0]; rank 0 writes out[b][10]
    if (rank == 0 && w < 10) {
        float s = 0.f;
        for (int k = l; k < DH; k += 32)
            s += hbuf[k] * Wc[(size_t)w * DH + k];
#pragma unroll
        for (int d = 16; d; d >>= 1) s += __shfl_xor_sync(~0u, s, d);
        if (l == 0) out[b * 10 + w] = s;
    }
    cl_sync();                                     // no early-exit vs peer DSMEM
}

extern "C" void kernel_launch(void* const* d_in, const int* in_sizes, int n_in,
                              void* d_out, int out_size) {
    const float* x   = (const float*)d_in[0];
    const float* Wlm = (const float*)d_in[1];
    const float* Wz  = (const float*)d_in[2];
    const float* Wr  = (const float*)d_in[3];
    const float* Wh  = (const float*)d_in[4];
    const float* Wc  = (const float*)d_in[5];
    float* out = (float*)d_out;

    const int smem_bytes = (96 * 512 + 1024 + 1024 + 32) * 4 + 24;
    cudaFuncSetAttribute(gru_kernel, cudaFuncAttributeNonPortableClusterSizeAllowed, 1);
    cudaFuncSetAttribute(gru_kernel, cudaFuncAttributeMaxDynamicSharedMemorySize, smem_bytes);

    gemm1_kernel<<<dim3(4, 256), 256>>>(x, Wlm);
    gemm2_kernel<<<dim3(12, 256), 256>>>(Wz, Wr, Wh);
    gru_kernel<<<BATCH * CLUSTER, 512, smem_bytes>>>(Wz, Wr, Wh, Wc, out);
}